// round 5
// baseline (speedup 1.0000x reference)
#include <cuda_runtime.h>
#include <cuda_bf16.h>

// Fixed problem sizes: N=100000 nodes, E=1280000 edges, D=64.
#define N_NODES 100000
#define N_EDGES 1280000
#define SCAN_BLK 256
#define NB_SCAN ((N_NODES + SCAN_BLK - 1) / SCAN_BLK)   // 391

// Device-global scratch (no cudaMalloc allowed).
__device__ float g_asrc[N_NODES];
__device__ float g_adst[N_NODES];
__device__ int   g_cnt[N_NODES];       // dst histogram
__device__ int   g_off[N_NODES];       // block-local exclusive prefix of cnt
__device__ int   g_part[NB_SCAN];      // per-block exclusive block prefix
__device__ int   g_rank[N_EDGES];      // rank of edge within its dst bin
__device__ uint2 g_pair[N_EDGES];      // (src, ew-bits) grouped by dst

// ---------------------------------------------------------------------------
// K1 (fused): per-node scores (16 threads/node, float4 each) + dst histogram
// with per-edge rank recording. Independent grid-stride jobs.
// ---------------------------------------------------------------------------
__global__ void scores_hist_kernel(const float4* __restrict__ x4,
                                   const float4* __restrict__ ws4,
                                   const float4* __restrict__ wd4,
                                   const int* __restrict__ dst_idx,
                                   int n_nodes, int n_edges) {
    int t = blockIdx.x * blockDim.x + threadIdx.x;

    // --- job A: node scores ---
    int node = t >> 4;
    int q = t & 15;
    if (node < n_nodes) {
        float4 v  = __ldg(x4 + (size_t)node * 16 + q);
        float4 ws = __ldg(ws4 + q);
        float4 wd = __ldg(wd4 + q);

        float ss = v.x * ws.x + v.y * ws.y + v.z * ws.z + v.w * ws.w;
        float sd = v.x * wd.x + v.y * wd.y + v.z * wd.z + v.w * wd.w;

        #pragma unroll
        for (int off = 8; off > 0; off >>= 1) {
            ss += __shfl_down_sync(0xffffffffu, ss, off, 16);
            sd += __shfl_down_sync(0xffffffffu, sd, off, 16);
        }
        if (q == 0) {
            g_asrc[node] = ss;
            g_adst[node] = sd;
        }
    }

    // --- job B: histogram + rank ---
    if (t < n_edges) {
        int d = __ldg(dst_idx + t);
        g_rank[t] = atomicAdd(&g_cnt[d], 1);
    }
}

// ---------------------------------------------------------------------------
// Scan phase A: per-block (256) exclusive scan of g_cnt -> g_off (local),
// block totals -> g_part.
// ---------------------------------------------------------------------------
__global__ void scanA_kernel(int n) {
    int i = blockIdx.x * SCAN_BLK + threadIdx.x;
    int v = (i < n) ? g_cnt[i] : 0;
    int lane = threadIdx.x & 31;
    int w = threadIdx.x >> 5;

    int incl = v;
    #pragma unroll
    for (int d = 1; d < 32; d <<= 1) {
        int u = __shfl_up_sync(0xffffffffu, incl, d);
        if (lane >= d) incl += u;
    }

    __shared__ int wsum[8];
    if (lane == 31) wsum[w] = incl;
    __syncthreads();
    if (w == 0 && lane < 8) {
        int s = wsum[lane];
        int si = s;
        #pragma unroll
        for (int d = 1; d < 8; d <<= 1) {
            int u = __shfl_up_sync(0x000000ffu, si, d);
            if (lane >= d) si += u;
        }
        wsum[lane] = si - s;   // exclusive warp-sum prefix
    }
    __syncthreads();

    int excl = incl - v + wsum[w];
    if (i < n) g_off[i] = excl;
    if (threadIdx.x == SCAN_BLK - 1) g_part[blockIdx.x] = incl + wsum[w];
}

// ---------------------------------------------------------------------------
// Scan phase B: exclusive scan of the 391 block totals, 2-level shfl scan.
// ---------------------------------------------------------------------------
__global__ void scanB_kernel(int nb) {
    int t = threadIdx.x;
    int lane = t & 31;
    int w = t >> 5;
    int v = (t < nb) ? g_part[t] : 0;

    int incl = v;
    #pragma unroll
    for (int d = 1; d < 32; d <<= 1) {
        int u = __shfl_up_sync(0xffffffffu, incl, d);
        if (lane >= d) incl += u;
    }

    __shared__ int wsum[16];
    if (lane == 31) wsum[w] = incl;
    __syncthreads();
    if (w == 0 && lane < 16) {
        int s = wsum[lane];
        int si = s;
        #pragma unroll
        for (int d = 1; d < 16; d <<= 1) {
            int u = __shfl_up_sync(0x0000ffffu, si, d);
            if (lane >= d) si += u;
        }
        wsum[lane] = si - s;
    }
    __syncthreads();

    if (t < nb) g_part[t] = incl - v + wsum[w];
}

// ---------------------------------------------------------------------------
// Permute (NO score reads): pack (src, ew) into the dst bin.
// Slot computed without atomics: local off + block prefix + rank.
// ---------------------------------------------------------------------------
__global__ void permute_kernel(const int* __restrict__ src_idx,
                               const int* __restrict__ dst_idx,
                               const float* __restrict__ ew,
                               int n_edges) {
    int e = blockIdx.x * blockDim.x + threadIdx.x;
    if (e >= n_edges) return;
    int s = __ldg(src_idx + e);
    int d = __ldg(dst_idx + e);
    float w = __ldg(ew + e);
    int p = g_off[d] + g_part[d >> 8] + g_rank[e];
    g_pair[p] = make_uint2((unsigned)s, __float_as_uint(w));
}

// ---------------------------------------------------------------------------
// Aggregate: 16 threads per dst node. Coefficient computed here:
// a_dst is loop-invariant; a_src[s] is a single broadcast read; tanh computed
// on lane 0 of each 16-group and shfl-broadcast. 2-way unroll for MLP.
// ---------------------------------------------------------------------------
__global__ void aggregate_kernel(const float4* __restrict__ x4,
                                 float4* __restrict__ out4,
                                 int n_nodes, int n_edges) {
    int t = blockIdx.x * blockDim.x + threadIdx.x;
    int node = t >> 4;
    int q = t & 15;
    if (node >= n_nodes) return;

    int beg = g_off[node] + g_part[node >> 8];
    int end = (node + 1 < n_nodes)
                  ? g_off[node + 1] + g_part[(node + 1) >> 8]
                  : n_edges;

    float adst = g_adst[node];   // broadcast, loop-invariant
    float4 acc = make_float4(0.f, 0.f, 0.f, 0.f);

    int i = beg;
    for (; i + 1 < end; i += 2) {
        uint2 p0 = __ldg(&g_pair[i]);
        uint2 p1 = __ldg(&g_pair[i + 1]);
        float4 x0 = __ldg(x4 + (size_t)p0.x * 16 + q);
        float4 x1 = __ldg(x4 + (size_t)p1.x * 16 + q);

        float c0 = 0.f, c1 = 0.f;
        if (q == 0) {
            float as0 = g_asrc[p0.x];
            float as1 = g_asrc[p1.x];
            c0 = tanhf(as0 + adst) * __uint_as_float(p0.y);
            c1 = tanhf(as1 + adst) * __uint_as_float(p1.y);
        }
        c0 = __shfl_sync(0xffffffffu, c0, 0, 16);
        c1 = __shfl_sync(0xffffffffu, c1, 0, 16);

        acc.x += c0 * x0.x; acc.y += c0 * x0.y;
        acc.z += c0 * x0.z; acc.w += c0 * x0.w;
        acc.x += c1 * x1.x; acc.y += c1 * x1.y;
        acc.z += c1 * x1.z; acc.w += c1 * x1.w;
    }
    if (i < end) {
        uint2 p0 = __ldg(&g_pair[i]);
        float4 x0 = __ldg(x4 + (size_t)p0.x * 16 + q);
        float c0 = 0.f;
        if (q == 0) {
            c0 = tanhf(g_asrc[p0.x] + adst) * __uint_as_float(p0.y);
        }
        c0 = __shfl_sync(0xffffffffu, c0, 0, 16);
        acc.x += c0 * x0.x; acc.y += c0 * x0.y;
        acc.z += c0 * x0.z; acc.w += c0 * x0.w;
    }

    out4[(size_t)node * 16 + q] = acc;
}

// ---------------------------------------------------------------------------
// Launch.
// Inputs: x[N*64] f32, w_src[64] f32, w_dst[64] f32, ew[E] f32,
//         src_idx[E] i32, dst_idx[E] i32.  Output: h[N*64] f32.
// ---------------------------------------------------------------------------
extern "C" void kernel_launch(void* const* d_in, const int* in_sizes, int n_in,
                              void* d_out, int out_size) {
    const float* x     = (const float*)d_in[0];
    const float* w_src = (const float*)d_in[1];
    const float* w_dst = (const float*)d_in[2];
    const float* ew    = (const float*)d_in[3];
    const int*   s_idx = (const int*)d_in[4];
    const int*   d_idx = (const int*)d_in[5];
    float* out = (float*)d_out;

    int n_nodes = in_sizes[0] / 64;
    int n_edges = in_sizes[3];

    // Zero the dst histogram.
    void* cnt_ptr = nullptr;
    cudaGetSymbolAddress(&cnt_ptr, g_cnt);
    cudaMemsetAsync(cnt_ptr, 0, sizeof(int) * (size_t)n_nodes);

    {   // fused scores + hist/rank: needs max(n_nodes*16, n_edges) threads
        long long total = (long long)n_nodes * 16;
        if ((long long)n_edges > total) total = n_edges;
        int blocks = (int)((total + 255) / 256);
        scores_hist_kernel<<<blocks, 256>>>((const float4*)x, (const float4*)w_src,
                                            (const float4*)w_dst, d_idx,
                                            n_nodes, n_edges);
    }
    {   // two-phase prefix scan
        int nb = (n_nodes + SCAN_BLK - 1) / SCAN_BLK;
        scanA_kernel<<<nb, SCAN_BLK>>>(n_nodes);
        scanB_kernel<<<1, 512>>>(nb);
    }
    {   // permute: pack (src, ew) by dst bin (atomic-free)
        int blocks = (n_edges + 255) / 256;
        permute_kernel<<<blocks, 256>>>(s_idx, d_idx, ew, n_edges);
    }
    {   // aggregate: 16 threads/node, coef fused here
        long long total = (long long)n_nodes * 16;
        int blocks = (int)((total + 255) / 256);
        aggregate_kernel<<<blocks, 256>>>((const float4*)x, (float4*)out,
                                          n_nodes, n_edges);
    }
}

// round 6
// speedup vs baseline: 1.5117x; 1.5117x over previous
#include <cuda_runtime.h>
#include <cuda_bf16.h>

// Fixed problem sizes: N=100000 nodes, E=1280000 edges, D=64.
#define N_NODES 100000
#define N_EDGES 1280000
#define SCAN_BLK 256
#define NB_SCAN ((N_NODES + SCAN_BLK - 1) / SCAN_BLK)   // 391

// Device-global scratch (no cudaMalloc allowed).
__device__ float g_asrc[N_NODES];
__device__ float g_adst[N_NODES];
__device__ int   g_cnt[N_NODES];         // dst histogram
__device__ int   g_off[N_NODES];         // block-local exclusive prefix of cnt
__device__ int   g_part[NB_SCAN];        // exclusive block prefix
__device__ int   g_rank[N_EDGES];        // rank of edge within its dst bin
__device__ uint2 g_combo[N_NODES + 1];   // per-dst: (adst-bits, base offset)
__device__ uint2 g_pair[N_EDGES];        // (src, coef-bits) grouped by dst

// ---------------------------------------------------------------------------
// K1 (fused): per-node scores (16 threads/node, float4 each) + dst histogram
// with per-edge rank recording. Independent grid-stride jobs.
// ---------------------------------------------------------------------------
__global__ void scores_hist_kernel(const float4* __restrict__ x4,
                                   const float4* __restrict__ ws4,
                                   const float4* __restrict__ wd4,
                                   const int* __restrict__ dst_idx,
                                   int n_nodes, int n_edges) {
    int t = blockIdx.x * blockDim.x + threadIdx.x;

    // --- job A: node scores ---
    int node = t >> 4;
    int q = t & 15;
    if (node < n_nodes) {
        float4 v  = __ldg(x4 + (size_t)node * 16 + q);
        float4 ws = __ldg(ws4 + q);
        float4 wd = __ldg(wd4 + q);

        float ss = v.x * ws.x + v.y * ws.y + v.z * ws.z + v.w * ws.w;
        float sd = v.x * wd.x + v.y * wd.y + v.z * wd.z + v.w * wd.w;

        #pragma unroll
        for (int off = 8; off > 0; off >>= 1) {
            ss += __shfl_down_sync(0xffffffffu, ss, off, 16);
            sd += __shfl_down_sync(0xffffffffu, sd, off, 16);
        }
        if (q == 0) {
            g_asrc[node] = ss;
            g_adst[node] = sd;
        }
    }

    // --- job B: histogram + rank ---
    if (t < n_edges) {
        int d = __ldg(dst_idx + t);
        g_rank[t] = atomicAdd(&g_cnt[d], 1);
    }
}

// ---------------------------------------------------------------------------
// Scan phase A: per-block (256) exclusive scan of g_cnt -> g_off (local),
// block totals -> g_part.
// ---------------------------------------------------------------------------
__global__ void scanA_kernel(int n) {
    int i = blockIdx.x * SCAN_BLK + threadIdx.x;
    int v = (i < n) ? g_cnt[i] : 0;
    int lane = threadIdx.x & 31;
    int w = threadIdx.x >> 5;

    int incl = v;
    #pragma unroll
    for (int d = 1; d < 32; d <<= 1) {
        int u = __shfl_up_sync(0xffffffffu, incl, d);
        if (lane >= d) incl += u;
    }

    __shared__ int wsum[8];
    if (lane == 31) wsum[w] = incl;
    __syncthreads();
    if (w == 0 && lane < 8) {
        int s = wsum[lane];
        int si = s;
        #pragma unroll
        for (int d = 1; d < 8; d <<= 1) {
            int u = __shfl_up_sync(0x000000ffu, si, d);
            if (lane >= d) si += u;
        }
        wsum[lane] = si - s;   // exclusive warp-sum prefix
    }
    __syncthreads();

    int excl = incl - v + wsum[w];
    if (i < n) g_off[i] = excl;
    if (threadIdx.x == SCAN_BLK - 1) g_part[blockIdx.x] = incl + wsum[w];
}

// ---------------------------------------------------------------------------
// Scan phase B: exclusive scan of the 391 block totals, 2-level shfl scan.
// ---------------------------------------------------------------------------
__global__ void scanB_kernel(int nb) {
    int t = threadIdx.x;
    int lane = t & 31;
    int w = t >> 5;
    int v = (t < nb) ? g_part[t] : 0;

    int incl = v;
    #pragma unroll
    for (int d = 1; d < 32; d <<= 1) {
        int u = __shfl_up_sync(0xffffffffu, incl, d);
        if (lane >= d) incl += u;
    }

    __shared__ int wsum[16];
    if (lane == 31) wsum[w] = incl;
    __syncthreads();
    if (w == 0 && lane < 16) {
        int s = wsum[lane];
        int si = s;
        #pragma unroll
        for (int d = 1; d < 16; d <<= 1) {
            int u = __shfl_up_sync(0x0000ffffu, si, d);
            if (lane >= d) si += u;
        }
        wsum[lane] = si - s;
    }
    __syncthreads();

    if (t < nb) g_part[t] = incl - v + wsum[w];
}

// ---------------------------------------------------------------------------
// Combo build: combo[d] = (adst[d] bits, final base offset). Streaming.
// ---------------------------------------------------------------------------
__global__ void combo_kernel(int n, int n_edges) {
    int i = blockIdx.x * blockDim.x + threadIdx.x;
    if (i < n) {
        int base = g_off[i] + g_part[i >> 8];
        g_combo[i] = make_uint2(__float_as_uint(g_adst[i]), (unsigned)base);
    }
    if (i == 0) g_combo[n] = make_uint2(0u, (unsigned)n_edges);
}

// ---------------------------------------------------------------------------
// Permute + fused coefficient. Random streams per edge: combo[d] (8B, one
// sector covers both adst and base), asrc[s] (4B), scattered pair write (8B).
// ---------------------------------------------------------------------------
__global__ void permute_kernel(const int* __restrict__ src_idx,
                               const int* __restrict__ dst_idx,
                               const float* __restrict__ ew,
                               int n_edges) {
    int e = blockIdx.x * blockDim.x + threadIdx.x;
    if (e >= n_edges) return;
    int s = __ldg(src_idx + e);
    int d = __ldg(dst_idx + e);
    float w = __ldg(ew + e);

    uint2 cb = g_combo[d];                       // (adst, base) one 8B read
    float adst = __uint_as_float(cb.x);
    float c = tanhf(g_asrc[s] + adst) * w;
    int p = (int)cb.y + g_rank[e];
    g_pair[p] = make_uint2((unsigned)s, __float_as_uint(c));
}

// ---------------------------------------------------------------------------
// Aggregate: 16 threads per dst node, register accumulation, 4-way unrolled
// gathers for MLP. No atomics; single float4 store per thread.
// ---------------------------------------------------------------------------
__global__ void aggregate_kernel(const float4* __restrict__ x4,
                                 float4* __restrict__ out4,
                                 int n_nodes) {
    int t = blockIdx.x * blockDim.x + threadIdx.x;
    int node = t >> 4;
    int q = t & 15;
    if (node >= n_nodes) return;

    int beg = (int)g_combo[node].y;
    int end = (int)g_combo[node + 1].y;

    float4 acc = make_float4(0.f, 0.f, 0.f, 0.f);

    int i = beg;
    for (; i + 3 < end; i += 4) {
        uint2 p0 = __ldg(&g_pair[i]);
        uint2 p1 = __ldg(&g_pair[i + 1]);
        uint2 p2 = __ldg(&g_pair[i + 2]);
        uint2 p3 = __ldg(&g_pair[i + 3]);
        float4 x0 = __ldg(x4 + (size_t)p0.x * 16 + q);
        float4 x1 = __ldg(x4 + (size_t)p1.x * 16 + q);
        float4 x2 = __ldg(x4 + (size_t)p2.x * 16 + q);
        float4 x3 = __ldg(x4 + (size_t)p3.x * 16 + q);
        float c0 = __uint_as_float(p0.y);
        float c1 = __uint_as_float(p1.y);
        float c2 = __uint_as_float(p2.y);
        float c3 = __uint_as_float(p3.y);
        acc.x += c0 * x0.x; acc.y += c0 * x0.y; acc.z += c0 * x0.z; acc.w += c0 * x0.w;
        acc.x += c1 * x1.x; acc.y += c1 * x1.y; acc.z += c1 * x1.z; acc.w += c1 * x1.w;
        acc.x += c2 * x2.x; acc.y += c2 * x2.y; acc.z += c2 * x2.z; acc.w += c2 * x2.w;
        acc.x += c3 * x3.x; acc.y += c3 * x3.y; acc.z += c3 * x3.z; acc.w += c3 * x3.w;
    }
    for (; i < end; ++i) {
        uint2 p0 = __ldg(&g_pair[i]);
        float4 x0 = __ldg(x4 + (size_t)p0.x * 16 + q);
        float c0 = __uint_as_float(p0.y);
        acc.x += c0 * x0.x; acc.y += c0 * x0.y; acc.z += c0 * x0.z; acc.w += c0 * x0.w;
    }

    out4[(size_t)node * 16 + q] = acc;
}

// ---------------------------------------------------------------------------
// Launch.
// Inputs: x[N*64] f32, w_src[64] f32, w_dst[64] f32, ew[E] f32,
//         src_idx[E] i32, dst_idx[E] i32.  Output: h[N*64] f32.
// ---------------------------------------------------------------------------
extern "C" void kernel_launch(void* const* d_in, const int* in_sizes, int n_in,
                              void* d_out, int out_size) {
    const float* x     = (const float*)d_in[0];
    const float* w_src = (const float*)d_in[1];
    const float* w_dst = (const float*)d_in[2];
    const float* ew    = (const float*)d_in[3];
    const int*   s_idx = (const int*)d_in[4];
    const int*   d_idx = (const int*)d_in[5];
    float* out = (float*)d_out;

    int n_nodes = in_sizes[0] / 64;
    int n_edges = in_sizes[3];

    // Zero the dst histogram.
    void* cnt_ptr = nullptr;
    cudaGetSymbolAddress(&cnt_ptr, g_cnt);
    cudaMemsetAsync(cnt_ptr, 0, sizeof(int) * (size_t)n_nodes);

    {   // fused scores + hist/rank: needs max(n_nodes*16, n_edges) threads
        long long total = (long long)n_nodes * 16;
        if ((long long)n_edges > total) total = n_edges;
        int blocks = (int)((total + 255) / 256);
        scores_hist_kernel<<<blocks, 256>>>((const float4*)x, (const float4*)w_src,
                                            (const float4*)w_dst, d_idx,
                                            n_nodes, n_edges);
    }
    {   // two-phase prefix scan
        int nb = (n_nodes + SCAN_BLK - 1) / SCAN_BLK;
        scanA_kernel<<<nb, SCAN_BLK>>>(n_nodes);
        scanB_kernel<<<1, 512>>>(nb);
    }
    {   // combo build (adst + base packed per dst)
        combo_kernel<<<(n_nodes + 255) / 256, 256>>>(n_nodes, n_edges);
    }
    {   // permute with fused coefficient computation (atomic-free)
        int blocks = (n_edges + 255) / 256;
        permute_kernel<<<blocks, 256>>>(s_idx, d_idx, ew, n_edges);
    }
    {   // aggregate: 16 threads/node
        long long total = (long long)n_nodes * 16;
        int blocks = (int)((total + 255) / 256);
        aggregate_kernel<<<blocks, 256>>>((const float4*)x, (float4*)out, n_nodes);
    }
}